// round 10
// baseline (speedup 1.0000x reference)
#include <cuda_runtime.h>
#include <math.h>

typedef unsigned long long ull;

#define Sn    64
#define Bz    256
#define VIN   128
#define VOUTn 128
#define UU    1024
#define EE    512
#define TDEC  25
#define G3U   3072
#define NQP   4224            // [gh(3072) | q(1024) | pred(128)]
#define GHKS  4
#define GIKS  3
#define QGHKS 2

// ---------------- scratch (static device globals; no allocation) ----------------
__device__ float g_gi_enc[(size_t)Sn*Bz*G3U];
__device__ float g_enc_out[(size_t)Sn*Bz*UU];     // pre-zeroed; masked rows stay 0
__device__ float g_enc_proj[(size_t)Sn*Bz*UU];
__device__ float g_h[Bz*UU];
__device__ float g_ghp[(size_t)GHKS*Bz*G3U];      // encoder gh partials
__device__ float g_gip[(size_t)GIKS*Bz*G3U];      // decoder gi (ctx part) partials
__device__ float g_qghp[(size_t)QGHKS*Bz*NQP];    // decoder [gh|q|pred] partials
__device__ float g_ctx[Bz*UU];
__device__ int   g_idx[Bz];
__device__ float g_Wqgh[(size_t)NQP*UU];          // [dec_Whh; W2_W; fc_W]
__device__ float g_bqgh[NQP];                     // [dec_bhh; W2_b; fc_b]
__device__ float g_T[(size_t)VOUTn*G3U];          // emb->gi table (incl dec_bih)
__device__ float g_Aemb[VOUTn*EE];
__device__ float g_zero[G3U];                     // zero bias

// ---------------- fast (~1e-7) transcendentals ----------------
__device__ __forceinline__ float f_ex2(float x){ float r; asm("ex2.approx.f32 %0, %1;" : "=f"(r) : "f"(x)); return r; }
__device__ __forceinline__ float f_rcp(float x){ float r; asm("rcp.approx.f32 %0, %1;" : "=f"(r) : "f"(x)); return r; }
__device__ __forceinline__ float fsigm(float x){ return f_rcp(1.f + f_ex2(-1.4426950408889634f*x)); }
__device__ __forceinline__ float ftanh(float x){ return 1.f - 2.f*f_rcp(1.f + f_ex2(2.8853900817779268f*x)); }

// ---------------- f32x2 helpers ----------------
#define DUP2(d, s)       asm("mov.b64 %0, {%1, %1};" : "=l"(d) : "f"(s))
#define FMA2(c, a, b)    asm("fma.rn.f32x2 %0, %1, %2, %0;" : "+l"(c) : "l"(a), "l"(b))
#define UNPK2(lo, hi, s) asm("mov.b64 {%0, %1}, %2;" : "=f"(lo), "=f"(hi) : "l"(s))

// ---------------- FFMA2 GEMM, double-buffered smem, 1 barrier/slab --------------
// C[M,N] = A[M,K] @ W[N,K]^T (+bias on slice z==0). Block 64x128, 128 thr, 8x8/thr.
// grid=(N/128, M/64, KS); slice z -> C + z*M*N, k in [nslab*z/KS, nslab*(z+1)/KS)*16.
// sorted-x_len early exit: tstep>=0: rows=batch; tstep<0: rows=s*256+b.
__global__ void __launch_bounds__(128) gemm2(
    const float* __restrict__ A, int lda,
    const float* __restrict__ W, int ldw,
    const float* __restrict__ bias, float* __restrict__ C,
    int M, int N, int K, int KS,
    const int* __restrict__ x_len, int tstep)
{
    const int bm = blockIdx.y * 64;
    if (x_len) {
        int t_eff = (tstep >= 0) ? tstep : (bm >> 8);
        int b_hi  = (tstep >= 0) ? (bm + 63) : ((bm & 255) + 63);
        if (x_len[b_hi] <= t_eff) return;
    }

    __shared__ float As[2][16][64];
    __shared__ float Ws[2][16][128];

    const int nslab = K >> 4;
    const int z  = blockIdx.z;
    const int k0 = ((nslab *  z     ) / KS) << 4;
    const int k1 = ((nslab * (z + 1)) / KS) << 4;
    C += (size_t)z * M * N;

    const int bn  = blockIdx.x * 128;
    const int tid = threadIdx.x;
    const int ty  = tid >> 4;
    const int tx  = tid & 15;
    const int ar  = tid >> 1;
    const int ak  = (tid & 1) << 3;

    ull acc[4][8];
    #pragma unroll
    for (int i = 0; i < 4; i++)
        #pragma unroll
        for (int j = 0; j < 8; j++) acc[i][j] = 0ull;

    const float* Arow = A + (size_t)(bm + ar) * lda + ak;
    const float* Wrow = W + (size_t)(bn + tid) * ldw;

    float4 pa0 = *(const float4*)(Arow + k0);
    float4 pa1 = *(const float4*)(Arow + k0 + 4);
    float4 pw0 = *(const float4*)(Wrow + k0);
    float4 pw1 = *(const float4*)(Wrow + k0 + 4);
    float4 pw2 = *(const float4*)(Wrow + k0 + 8);
    float4 pw3 = *(const float4*)(Wrow + k0 + 12);

    int cur = 0;
    for (int kb = k0; kb < k1; kb += 16) {
        As[cur][ak+0][ar] = pa0.x; As[cur][ak+1][ar] = pa0.y; As[cur][ak+2][ar] = pa0.z; As[cur][ak+3][ar] = pa0.w;
        As[cur][ak+4][ar] = pa1.x; As[cur][ak+5][ar] = pa1.y; As[cur][ak+6][ar] = pa1.z; As[cur][ak+7][ar] = pa1.w;
        Ws[cur][ 0][tid] = pw0.x; Ws[cur][ 1][tid] = pw0.y; Ws[cur][ 2][tid] = pw0.z; Ws[cur][ 3][tid] = pw0.w;
        Ws[cur][ 4][tid] = pw1.x; Ws[cur][ 5][tid] = pw1.y; Ws[cur][ 6][tid] = pw1.z; Ws[cur][ 7][tid] = pw1.w;
        Ws[cur][ 8][tid] = pw2.x; Ws[cur][ 9][tid] = pw2.y; Ws[cur][10][tid] = pw2.z; Ws[cur][11][tid] = pw2.w;
        Ws[cur][12][tid] = pw3.x; Ws[cur][13][tid] = pw3.y; Ws[cur][14][tid] = pw3.z; Ws[cur][15][tid] = pw3.w;
        __syncthreads();

        if (kb + 16 < k1) {        // prefetch next slab; hides under compute
            pa0 = *(const float4*)(Arow + kb + 16);
            pa1 = *(const float4*)(Arow + kb + 20);
            pw0 = *(const float4*)(Wrow + kb + 16);
            pw1 = *(const float4*)(Wrow + kb + 20);
            pw2 = *(const float4*)(Wrow + kb + 24);
            pw3 = *(const float4*)(Wrow + kb + 28);
        }

        #pragma unroll
        for (int kk = 0; kk < 16; kk++) {
            const ull* ap = (const ull*)&As[cur][kk][ty << 3];
            ull a2_0 = ap[0], a2_1 = ap[1], a2_2 = ap[2], a2_3 = ap[3];
            const float* wp = &Ws[cur][kk][tx << 3];
            float4 wv0 = *(const float4*)wp;
            float4 wv1 = *(const float4*)(wp + 4);
            ull wd[8];
            DUP2(wd[0], wv0.x); DUP2(wd[1], wv0.y); DUP2(wd[2], wv0.z); DUP2(wd[3], wv0.w);
            DUP2(wd[4], wv1.x); DUP2(wd[5], wv1.y); DUP2(wd[6], wv1.z); DUP2(wd[7], wv1.w);
            #pragma unroll
            for (int j = 0; j < 8; j++) {
                FMA2(acc[0][j], a2_0, wd[j]);
                FMA2(acc[1][j], a2_1, wd[j]);
                FMA2(acc[2][j], a2_2, wd[j]);
                FMA2(acc[3][j], a2_3, wd[j]);
            }
        }
        cur ^= 1;
    }

    const int col = bn + (tx << 3);
    float bv[8];
    #pragma unroll
    for (int j = 0; j < 8; j++) bv[j] = (z == 0) ? bias[col + j] : 0.f;

    #pragma unroll
    for (int i = 0; i < 4; i++) {
        const int r0 = bm + (ty << 3) + 2*i;
        float lo[8], hi[8];
        #pragma unroll
        for (int j = 0; j < 8; j++) {
            float l, h;
            UNPK2(l, h, acc[i][j]);
            lo[j] = l + bv[j];
            hi[j] = h + bv[j];
        }
        float4* c0 = (float4*)(C + (size_t)r0     * N + col);
        float4* c1 = (float4*)(C + (size_t)(r0+1) * N + col);
        c0[0] = make_float4(lo[0], lo[1], lo[2], lo[3]);
        c0[1] = make_float4(lo[4], lo[5], lo[6], lo[7]);
        c1[0] = make_float4(hi[0], hi[1], hi[2], hi[3]);
        c1[1] = make_float4(hi[4], hi[5], hi[6], hi[7]);
    }
}

// ---------------- encoder GRU gate (float4, active rows only) ----------------
__global__ void enc_gate(const float* __restrict__ gi, const float* __restrict__ ghp,
                         float* __restrict__ h, float* __restrict__ enc_out_t,
                         const int* __restrict__ x_len, int t)
{
    int i = blockIdx.x * blockDim.x + threadIdx.x;       // float4 index, 0..Bz*UU/4
    int b = i >> 8;
    if (t >= x_len[b]) return;
    int u = (i & 255) << 2;
    size_t base = (size_t)b * G3U + u;
    const size_t MN = (size_t)Bz * G3U;
    float4 gr = *(const float4*)(ghp + base);
    float4 gz = *(const float4*)(ghp + base + UU);
    float4 gn = *(const float4*)(ghp + base + 2*UU);
    #pragma unroll
    for (int s = 1; s < GHKS; s++) {
        float4 a = *(const float4*)(ghp + s*MN + base);
        float4 c = *(const float4*)(ghp + s*MN + base + UU);
        float4 d = *(const float4*)(ghp + s*MN + base + 2*UU);
        gr.x+=a.x; gr.y+=a.y; gr.z+=a.z; gr.w+=a.w;
        gz.x+=c.x; gz.y+=c.y; gz.z+=c.z; gz.w+=c.w;
        gn.x+=d.x; gn.y+=d.y; gn.z+=d.z; gn.w+=d.w;
    }
    float4 ir = *(const float4*)(gi + base);
    float4 iz = *(const float4*)(gi + base + UU);
    float4 in = *(const float4*)(gi + base + 2*UU);
    float4 hv = *(const float4*)(h + (size_t)b*UU + u);
    float4 hn;
    {
        float r, z, n;
        r = fsigm(ir.x+gr.x); z = fsigm(iz.x+gz.x); n = ftanh(in.x + r*gn.x); hn.x = (1.f-z)*n + z*hv.x;
        r = fsigm(ir.y+gr.y); z = fsigm(iz.y+gz.y); n = ftanh(in.y + r*gn.y); hn.y = (1.f-z)*n + z*hv.y;
        r = fsigm(ir.z+gr.z); z = fsigm(iz.z+gz.z); n = ftanh(in.z + r*gn.z); hn.z = (1.f-z)*n + z*hv.z;
        r = fsigm(ir.w+gr.w); z = fsigm(iz.w+gz.w); n = ftanh(in.w + r*gn.w); hn.w = (1.f-z)*n + z*hv.w;
    }
    *(float4*)(h + (size_t)b*UU + u)         = hn;
    *(float4*)(enc_out_t + (size_t)b*UU + u) = hn;
}

// ---------------- decoder GRU gate (float4; gi partials + emb table + qgh partials)
__global__ void dec_gate(const float* __restrict__ gip, const float* __restrict__ qghp,
                         const float* __restrict__ T, const int* __restrict__ idx,
                         float* __restrict__ h)
{
    int i = blockIdx.x * blockDim.x + threadIdx.x;       // float4 index
    int b = i >> 8;
    int u = (i & 255) << 2;
    size_t gbase = (size_t)b * G3U + u;
    const size_t MN3 = (size_t)Bz * G3U;
    const float* tb = T + (size_t)idx[b] * G3U + u;
    float4 ir = *(const float4*)(tb);
    float4 iz = *(const float4*)(tb + UU);
    float4 in = *(const float4*)(tb + 2*UU);
    #pragma unroll
    for (int s = 0; s < GIKS; s++) {
        float4 a = *(const float4*)(gip + s*MN3 + gbase);
        float4 c = *(const float4*)(gip + s*MN3 + gbase + UU);
        float4 d = *(const float4*)(gip + s*MN3 + gbase + 2*UU);
        ir.x+=a.x; ir.y+=a.y; ir.z+=a.z; ir.w+=a.w;
        iz.x+=c.x; iz.y+=c.y; iz.z+=c.z; iz.w+=c.w;
        in.x+=d.x; in.y+=d.y; in.z+=d.z; in.w+=d.w;
    }
    size_t qbase = (size_t)b * NQP + u;
    const size_t MNq = (size_t)Bz * NQP;
    float4 gr = make_float4(0,0,0,0), gz = gr, gn = gr;
    #pragma unroll
    for (int s = 0; s < QGHKS; s++) {
        float4 a = *(const float4*)(qghp + s*MNq + qbase);
        float4 c = *(const float4*)(qghp + s*MNq + qbase + UU);
        float4 d = *(const float4*)(qghp + s*MNq + qbase + 2*UU);
        gr.x+=a.x; gr.y+=a.y; gr.z+=a.z; gr.w+=a.w;
        gz.x+=c.x; gz.y+=c.y; gz.z+=c.z; gz.w+=c.w;
        gn.x+=d.x; gn.y+=d.y; gn.z+=d.z; gn.w+=d.w;
    }
    float4 hv = *(const float4*)(h + (size_t)b*UU + u);
    float4 hn;
    {
        float r, z, n;
        r = fsigm(ir.x+gr.x); z = fsigm(iz.x+gz.x); n = ftanh(in.x + r*gn.x); hn.x = (1.f-z)*n + z*hv.x;
        r = fsigm(ir.y+gr.y); z = fsigm(iz.y+gz.y); n = ftanh(in.y + r*gn.y); hn.y = (1.f-z)*n + z*hv.y;
        r = fsigm(ir.z+gr.z); z = fsigm(iz.z+gz.z); n = ftanh(in.z + r*gn.z); hn.z = (1.f-z)*n + z*hv.z;
        r = fsigm(ir.w+gr.w); z = fsigm(iz.w+gz.w); n = ftanh(in.w + r*gn.w); hn.w = (1.f-z)*n + z*hv.w;
    }
    *(float4*)(h + (size_t)b*UU + u) = hn;
}

// ---------------- fused attention: q-sum + logits + softmax + ctx ----------------
__global__ void __launch_bounds__(256) fused_attn(
    const float* __restrict__ qghp, const float* __restrict__ enc_proj,
    const float* __restrict__ enc_out,
    const float* __restrict__ V_W, const float* __restrict__ V_b,
    const float* __restrict__ W1_b, const int* __restrict__ x_len,
    float* __restrict__ ctx)
{
    __shared__ float qs[UU];
    __shared__ float vs[UU];
    __shared__ float wb[UU];
    __shared__ float lg[Sn];
    const int b = blockIdx.x, tid = threadIdx.x;
    const int w = tid >> 5, lane = tid & 31;
    const size_t MNq = (size_t)Bz * NQP;
    const size_t qoff = (size_t)b * NQP + 3*UU;

    #pragma unroll
    for (int k = 0; k < 4; k++) {
        int u = tid + 256*k;
        qs[u] = qghp[qoff + u] + qghp[MNq + qoff + u];
        vs[u] = V_W[u];
        wb[u] = W1_b[u];
    }
    __syncthreads();

    const int L = x_len[b];
    for (int s = w; s < L; s += 8) {
        const float4* ep = (const float4*)(enc_proj + ((size_t)s * Bz + b) * UU);
        const float4* q4 = (const float4*)qs;
        const float4* v4 = (const float4*)vs;
        float sum = 0.f;
        #pragma unroll
        for (int it = 0; it < 8; it++) {
            int u = lane + 32*it;
            float4 e = ep[u], qq = q4[u], vv = v4[u];
            sum += ftanh(e.x + qq.x) * vv.x + ftanh(e.y + qq.y) * vv.y
                 + ftanh(e.z + qq.z) * vv.z + ftanh(e.w + qq.w) * vv.w;
        }
        #pragma unroll
        for (int off = 16; off; off >>= 1)
            sum += __shfl_down_sync(0xffffffffu, sum, off);
        if (lane == 0) lg[s] = sum + V_b[0];
    }
    if (w == 0 && L < Sn) {      // masked s: enc_proj row == W1_b analytically
        const float4* q4 = (const float4*)qs;
        const float4* v4 = (const float4*)vs;
        const float4* w4 = (const float4*)wb;
        float sum = 0.f;
        #pragma unroll
        for (int it = 0; it < 8; it++) {
            int u = lane + 32*it;
            float4 e = w4[u], qq = q4[u], vv = v4[u];
            sum += ftanh(e.x + qq.x) * vv.x + ftanh(e.y + qq.y) * vv.y
                 + ftanh(e.z + qq.z) * vv.z + ftanh(e.w + qq.w) * vv.w;
        }
        #pragma unroll
        for (int off = 16; off; off >>= 1)
            sum += __shfl_down_sync(0xffffffffu, sum, off);
        if (lane == 0) {
            float c = sum + V_b[0];
            for (int s = L; s < Sn; s++) lg[s] = c;
        }
    }
    __syncthreads();

    if (w == 0) {
        float v0 = lg[lane], v1 = lg[lane + 32];
        float mx = fmaxf(v0, v1);
        #pragma unroll
        for (int off = 16; off; off >>= 1)
            mx = fmaxf(mx, __shfl_xor_sync(0xffffffffu, mx, off));
        float e0 = f_ex2(1.4426950408889634f * (v0 - mx));
        float e1 = f_ex2(1.4426950408889634f * (v1 - mx));
        float sm = e0 + e1;
        #pragma unroll
        for (int off = 16; off; off >>= 1)
            sm += __shfl_xor_sync(0xffffffffu, sm, off);
        float inv = f_rcp(sm);
        lg[lane]      = e0 * inv;
        lg[lane + 32] = e1 * inv;
    }
    __syncthreads();

    float4 c4 = make_float4(0,0,0,0);
    const int u = tid << 2;
    for (int s = 0; s < L; s++) {
        float a = lg[s];
        float4 eo = *(const float4*)(enc_out + ((size_t)s * Bz + b) * UU + u);
        c4.x += a * eo.x; c4.y += a * eo.y; c4.z += a * eo.z; c4.w += a * eo.w;
    }
    *(float4*)(ctx + (size_t)b * UU + u) = c4;
}

// ---------------- pred: sum 2 qgh partials (cols 4096..4223) + write + argmax ----
__global__ void pred_argmax(const float* __restrict__ qghp,
                            float* __restrict__ out_t, int* __restrict__ idx)
{
    int b = blockIdx.x;
    int t = threadIdx.x;            // 128 threads
    const size_t MNq = (size_t)Bz * NQP;
    size_t base = (size_t)b * NQP + 4096 + t;
    float v = qghp[base] + qghp[MNq + base];
    out_t[(size_t)b * VOUTn + t] = v;

    __shared__ float sv[VOUTn];
    __shared__ int   si[VOUTn];
    sv[t] = v; si[t] = t;
    __syncthreads();
    #pragma unroll
    for (int off = 64; off; off >>= 1) {
        if (t < off) {
            float v2 = sv[t+off]; int i2 = si[t+off];
            if (v2 > sv[t] || (v2 == sv[t] && i2 < si[t])) { sv[t] = v2; si[t] = i2; }
        }
        __syncthreads();
    }
    if (t == 0) idx[b] = si[0];
}

// ---------------- one-time prep & init ----------------
__global__ void prep(const float* __restrict__ dec_Whh, const float* __restrict__ W2_W,
                     const float* __restrict__ fc_W,
                     const float* __restrict__ dec_bhh, const float* __restrict__ W2_b,
                     const float* __restrict__ fc_b,
                     const float* __restrict__ o2h_W,   const float* __restrict__ o2h_b,
                     float* __restrict__ Wqgh, float* __restrict__ bqgh,
                     float* __restrict__ Aemb)
{
    int i = blockIdx.x * 256 + threadIdx.x;          // 0 .. NQP*UU-1
    float wv;
    if (i < G3U*UU)            wv = dec_Whh[i];
    else if (i < (G3U+UU)*UU)  wv = W2_W[i - G3U*UU];
    else                       wv = fc_W[i - (G3U+UU)*UU];
    Wqgh[i] = wv;
    if (i < NQP) {
        float bv;
        if (i < G3U)           bv = dec_bhh[i];
        else if (i < G3U+UU)   bv = W2_b[i - G3U];
        else                   bv = fc_b[i - G3U - UU];
        bqgh[i] = bv;
    }
    if (i < VOUTn*EE) {
        int v = i / EE, e = i % EE;
        Aemb[i] = o2h_W[(size_t)e * VOUTn + v] + o2h_b[e];
    }
}

__global__ void init_all(float4* __restrict__ enc_out, float4* __restrict__ h,
                         float4* __restrict__ out0, int* __restrict__ idx)
{
    size_t i = (size_t)blockIdx.x * 256 + threadIdx.x;    // float4 idx, 0..S*B*U/4-1
    float4 zz = make_float4(0,0,0,0);
    enc_out[i] = zz;
    if (i < Bz*UU/4)    h[i] = zz;
    if (i < Bz*VOUTn/4) out0[i] = ((i & 31) == 0) ? make_float4(1,0,0,0) : zz;
    if (i < Bz)         idx[i] = 0;
}

// ---------------- driver ----------------
extern "C" void kernel_launch(void* const* d_in, const int* in_sizes, int n_in,
                              void* d_out, int out_size)
{
    const float* x       = (const float*)d_in[0];
    const int*   x_len   = (const int*)  d_in[1];
    const float* enc_Wih = (const float*)d_in[2];
    const float* enc_Whh = (const float*)d_in[3];
    const float* enc_bih = (const float*)d_in[4];
    const float* enc_bhh = (const float*)d_in[5];
    const float* dec_Wih = (const float*)d_in[6];
    const float* dec_Whh = (const float*)d_in[7];
    const float* dec_bih = (const float*)d_in[8];
    const float* dec_bhh = (const float*)d_in[9];
    const float* o2h_W   = (const float*)d_in[10];
    const float* o2h_b   = (const float*)d_in[11];
    const float* fc_W    = (const float*)d_in[12];
    const float* fc_b    = (const float*)d_in[13];
    const float* W1_W    = (const float*)d_in[14];
    const float* W1_b    = (const float*)d_in[15];
    const float* W2_W    = (const float*)d_in[16];
    const float* W2_b    = (const float*)d_in[17];
    const float* V_W     = (const float*)d_in[18];
    const float* V_b     = (const float*)d_in[19];
    float* out = (float*)d_out;

    float *gi_enc, *enc_out, *enc_proj, *h, *ghp, *gip, *qghp, *ctx;
    float *Wqgh, *bqgh, *T, *Aemb, *zerob;
    int* idx;
    cudaGetSymbolAddress((void**)&gi_enc,   g_gi_enc);
    cudaGetSymbolAddress((void**)&enc_out,  g_enc_out);
    cudaGetSymbolAddress((void**)&enc_proj, g_enc_proj);
    cudaGetSymbolAddress((void**)&h,        g_h);
    cudaGetSymbolAddress((void**)&ghp,      g_ghp);
    cudaGetSymbolAddress((void**)&gip,      g_gip);
    cudaGetSymbolAddress((void**)&qghp,     g_qghp);
    cudaGetSymbolAddress((void**)&ctx,      g_ctx);
    cudaGetSymbolAddress((void**)&idx,      g_idx);
    cudaGetSymbolAddress((void**)&Wqgh,     g_Wqgh);
    cudaGetSymbolAddress((void**)&bqgh,     g_bqgh);
    cudaGetSymbolAddress((void**)&T,        g_T);
    cudaGetSymbolAddress((void**)&Aemb,     g_Aemb);
    cudaGetSymbolAddress((void**)&zerob,    g_zero);

    // ---- one-time prep ----
    prep<<<(NQP*UU)/256, 256>>>(dec_Whh, W2_W, fc_W, dec_bhh, W2_b, fc_b,
                                o2h_W, o2h_b, Wqgh, bqgh, Aemb);
    init_all<<<((size_t)Sn*Bz*UU/4)/256, 256>>>((float4*)enc_out, (float4*)h,
                                                (float4*)out, idx);
    // emb->gi table: T[128,3U] = Aemb @ dec_Wih[:,U:U+E]^T + dec_bih
    gemm2<<<dim3(G3U/128, VOUTn/64, 1), 128>>>(Aemb, EE, dec_Wih + UU, UU+EE,
                                               dec_bih, T, VOUTn, G3U, EE, 1,
                                               nullptr, -1);
    // encoder input gates, all steps (skip fully-masked tiles)
    gemm2<<<dim3(G3U/128, (Sn*Bz)/64, 1), 128>>>(x, VIN, enc_Wih, VIN, enc_bih,
                                                 gi_enc, Sn*Bz, G3U, VIN, 1,
                                                 x_len, -1);

    // ---- Encoder: 64 sequential GRU steps (active-suffix only) ----
    for (int t = 0; t < Sn; t++) {
        gemm2<<<dim3(G3U/128, Bz/64, GHKS), 128>>>(h, UU, enc_Whh, UU, enc_bhh,
                                                   ghp, Bz, G3U, UU, GHKS,
                                                   x_len, t);
        enc_gate<<<(Bz*UU/4)/256, 256>>>(gi_enc + (size_t)t*Bz*G3U, ghp, h,
                                         enc_out + (size_t)t*Bz*UU, x_len, t);
    }

    // enc_proj = enc_out @ W1^T + b
    gemm2<<<dim3(UU/128, (Sn*Bz)/64, 1), 128>>>(enc_out, UU, W1_W, UU, W1_b,
                                                enc_proj, Sn*Bz, UU, UU, 1,
                                                x_len, -1);

    // ---- Decoder: 24 steps; [gh|q|pred] in one GEMM; pred_k from step k+1's GEMM
    for (int k = 1; k <= TDEC - 1; k++) {
        gemm2<<<dim3(NQP/128, Bz/64, QGHKS), 128>>>(h, UU, Wqgh, UU, bqgh,
                                                    qghp, Bz, NQP, UU, QGHKS,
                                                    nullptr, -1);
        if (k >= 2)   // pred slice of this GEMM = fc(h_{k-1}) = out[k-1]
            pred_argmax<<<Bz, 128>>>(qghp, out + (size_t)(k-1)*Bz*VOUTn, idx);
        fused_attn<<<Bz, 256>>>(qghp, enc_proj, enc_out, V_W, V_b, W1_b,
                                x_len, ctx);
        gemm2<<<dim3(G3U/128, Bz/64, GIKS), 128>>>(ctx, UU, dec_Wih, UU+EE,
                                                   zerob, gip, Bz, G3U, UU,
                                                   GIKS, nullptr, -1);
        dec_gate<<<(Bz*UU/4)/256, 256>>>(gip, qghp, T, idx, h);
    }
    // final pred: fc(h_24) = out[24]
    gemm2<<<dim3(NQP/128, Bz/64, QGHKS), 128>>>(h, UU, Wqgh, UU, bqgh,
                                                qghp, Bz, NQP, UU, QGHKS,
                                                nullptr, -1);
    pred_argmax<<<Bz, 128>>>(qghp, out + (size_t)(TDEC-1)*Bz*VOUTn, idx);
}

// round 11
// speedup vs baseline: 1.1240x; 1.1240x over previous
#include <cuda_runtime.h>
#include <math.h>

typedef unsigned long long ull;

#define Sn    64
#define Bz    256
#define VIN   128
#define VOUTn 128
#define UU    1024
#define EE    512
#define TDEC  25
#define G3U   3072
#define NQP   4224            // [gh(3072) | q(1024) | pred(128)]
#define GHKS  6
#define GIKS  6
#define QGHKS 4

// ---------------- scratch (static device globals; no allocation) ----------------
__device__ float g_gi_enc[(size_t)Sn*Bz*G3U];
__device__ float g_enc_out[(size_t)Sn*Bz*UU];     // pre-zeroed; masked rows stay 0
__device__ float g_enc_proj[(size_t)Sn*Bz*UU];
__device__ float g_h[Bz*UU];
__device__ float g_ghp[(size_t)GHKS*Bz*G3U];      // encoder gh partials
__device__ float g_gip[(size_t)GIKS*Bz*G3U];      // decoder gi (ctx part) partials
__device__ float g_qghp[(size_t)QGHKS*Bz*NQP];    // decoder [gh|q|pred] partials
__device__ float g_ctx[Bz*UU];
__device__ int   g_idx[Bz];
__device__ float g_Wqgh[(size_t)NQP*UU];          // [dec_Whh; W2_W; fc_W]
__device__ float g_bqgh[NQP];                     // [dec_bhh; W2_b; fc_b]
__device__ float g_T[(size_t)VOUTn*G3U];          // emb->gi table (incl dec_bih)
__device__ float g_Aemb[VOUTn*EE];
__device__ float g_zero[G3U];                     // zero bias

// ---------------- fast (~1e-7) transcendentals ----------------
__device__ __forceinline__ float f_ex2(float x){ float r; asm("ex2.approx.f32 %0, %1;" : "=f"(r) : "f"(x)); return r; }
__device__ __forceinline__ float f_rcp(float x){ float r; asm("rcp.approx.f32 %0, %1;" : "=f"(r) : "f"(x)); return r; }
__device__ __forceinline__ float fsigm(float x){ return f_rcp(1.f + f_ex2(-1.4426950408889634f*x)); }
__device__ __forceinline__ float ftanh(float x){ return 1.f - 2.f*f_rcp(1.f + f_ex2(2.8853900817779268f*x)); }

// ---------------- f32x2 helpers ----------------
#define DUP2(d, s)       asm("mov.b64 %0, {%1, %1};" : "=l"(d) : "f"(s))
#define FMA2(c, a, b)    asm("fma.rn.f32x2 %0, %1, %2, %0;" : "+l"(c) : "l"(a), "l"(b))
#define UNPK2(lo, hi, s) asm("mov.b64 {%0, %1}, %2;" : "=f"(lo), "=f"(hi) : "l"(s))

// ---------------- FFMA2 GEMM, double-buffered smem, 1 barrier/slab --------------
// C[M,N] = A[M,K] @ W[N,K]^T (+bias on slice z==0). Block 64x128, 128 thr, 8x8/thr.
// grid=(N/128, M/64, KS); slice z -> C + z*M*N, k in [nslab*z/KS, nslab*(z+1)/KS)*16.
// sorted-x_len early exit: tstep>=0: rows=batch; tstep<0: rows=s*256+b.
__global__ void __launch_bounds__(128) gemm2(
    const float* __restrict__ A, int lda,
    const float* __restrict__ W, int ldw,
    const float* __restrict__ bias, float* __restrict__ C,
    int M, int N, int K, int KS,
    const int* __restrict__ x_len, int tstep)
{
    const int bm = blockIdx.y * 64;
    if (x_len) {
        int t_eff = (tstep >= 0) ? tstep : (bm >> 8);
        int b_hi  = (tstep >= 0) ? (bm + 63) : ((bm & 255) + 63);
        if (x_len[b_hi] <= t_eff) return;
    }

    __shared__ float As[2][16][64];
    __shared__ float Ws[2][16][128];

    const int nslab = K >> 4;
    const int z  = blockIdx.z;
    const int k0 = ((nslab *  z     ) / KS) << 4;
    const int k1 = ((nslab * (z + 1)) / KS) << 4;
    C += (size_t)z * M * N;

    const int bn  = blockIdx.x * 128;
    const int tid = threadIdx.x;
    const int ty  = tid >> 4;
    const int tx  = tid & 15;
    const int ar  = tid >> 1;
    const int ak  = (tid & 1) << 3;

    ull acc[4][8];
    #pragma unroll
    for (int i = 0; i < 4; i++)
        #pragma unroll
        for (int j = 0; j < 8; j++) acc[i][j] = 0ull;

    const float* Arow = A + (size_t)(bm + ar) * lda + ak;
    const float* Wrow = W + (size_t)(bn + tid) * ldw;

    float4 pa0 = *(const float4*)(Arow + k0);
    float4 pa1 = *(const float4*)(Arow + k0 + 4);
    float4 pw0 = *(const float4*)(Wrow + k0);
    float4 pw1 = *(const float4*)(Wrow + k0 + 4);
    float4 pw2 = *(const float4*)(Wrow + k0 + 8);
    float4 pw3 = *(const float4*)(Wrow + k0 + 12);

    int cur = 0;
    for (int kb = k0; kb < k1; kb += 16) {
        As[cur][ak+0][ar] = pa0.x; As[cur][ak+1][ar] = pa0.y; As[cur][ak+2][ar] = pa0.z; As[cur][ak+3][ar] = pa0.w;
        As[cur][ak+4][ar] = pa1.x; As[cur][ak+5][ar] = pa1.y; As[cur][ak+6][ar] = pa1.z; As[cur][ak+7][ar] = pa1.w;
        Ws[cur][ 0][tid] = pw0.x; Ws[cur][ 1][tid] = pw0.y; Ws[cur][ 2][tid] = pw0.z; Ws[cur][ 3][tid] = pw0.w;
        Ws[cur][ 4][tid] = pw1.x; Ws[cur][ 5][tid] = pw1.y; Ws[cur][ 6][tid] = pw1.z; Ws[cur][ 7][tid] = pw1.w;
        Ws[cur][ 8][tid] = pw2.x; Ws[cur][ 9][tid] = pw2.y; Ws[cur][10][tid] = pw2.z; Ws[cur][11][tid] = pw2.w;
        Ws[cur][12][tid] = pw3.x; Ws[cur][13][tid] = pw3.y; Ws[cur][14][tid] = pw3.z; Ws[cur][15][tid] = pw3.w;
        __syncthreads();

        if (kb + 16 < k1) {        // prefetch next slab; hides under compute
            pa0 = *(const float4*)(Arow + kb + 16);
            pa1 = *(const float4*)(Arow + kb + 20);
            pw0 = *(const float4*)(Wrow + kb + 16);
            pw1 = *(const float4*)(Wrow + kb + 20);
            pw2 = *(const float4*)(Wrow + kb + 24);
            pw3 = *(const float4*)(Wrow + kb + 28);
        }

        #pragma unroll
        for (int kk = 0; kk < 16; kk++) {
            const ull* ap = (const ull*)&As[cur][kk][ty << 3];
            ull a2_0 = ap[0], a2_1 = ap[1], a2_2 = ap[2], a2_3 = ap[3];
            const float* wp = &Ws[cur][kk][tx << 3];
            float4 wv0 = *(const float4*)wp;
            float4 wv1 = *(const float4*)(wp + 4);
            ull wd[8];
            DUP2(wd[0], wv0.x); DUP2(wd[1], wv0.y); DUP2(wd[2], wv0.z); DUP2(wd[3], wv0.w);
            DUP2(wd[4], wv1.x); DUP2(wd[5], wv1.y); DUP2(wd[6], wv1.z); DUP2(wd[7], wv1.w);
            #pragma unroll
            for (int j = 0; j < 8; j++) {
                FMA2(acc[0][j], a2_0, wd[j]);
                FMA2(acc[1][j], a2_1, wd[j]);
                FMA2(acc[2][j], a2_2, wd[j]);
                FMA2(acc[3][j], a2_3, wd[j]);
            }
        }
        cur ^= 1;
    }

    const int col = bn + (tx << 3);
    float bv[8];
    #pragma unroll
    for (int j = 0; j < 8; j++) bv[j] = (z == 0) ? bias[col + j] : 0.f;

    #pragma unroll
    for (int i = 0; i < 4; i++) {
        const int r0 = bm + (ty << 3) + 2*i;
        float lo[8], hi[8];
        #pragma unroll
        for (int j = 0; j < 8; j++) {
            float l, h;
            UNPK2(l, h, acc[i][j]);
            lo[j] = l + bv[j];
            hi[j] = h + bv[j];
        }
        float4* c0 = (float4*)(C + (size_t)r0     * N + col);
        float4* c1 = (float4*)(C + (size_t)(r0+1) * N + col);
        c0[0] = make_float4(lo[0], lo[1], lo[2], lo[3]);
        c0[1] = make_float4(lo[4], lo[5], lo[6], lo[7]);
        c1[0] = make_float4(hi[0], hi[1], hi[2], hi[3]);
        c1[1] = make_float4(hi[4], hi[5], hi[6], hi[7]);
    }
}

// ---------------- encoder GRU gate (float4, active rows only) ----------------
__global__ void enc_gate(const float* __restrict__ gi, const float* __restrict__ ghp,
                         float* __restrict__ h, float* __restrict__ enc_out_t,
                         const int* __restrict__ x_len, int t)
{
    int i = blockIdx.x * blockDim.x + threadIdx.x;       // float4 index, 0..Bz*UU/4
    int b = i >> 8;
    if (t >= x_len[b]) return;
    int u = (i & 255) << 2;
    size_t base = (size_t)b * G3U + u;
    const size_t MN = (size_t)Bz * G3U;
    float4 gr = *(const float4*)(ghp + base);
    float4 gz = *(const float4*)(ghp + base + UU);
    float4 gn = *(const float4*)(ghp + base + 2*UU);
    #pragma unroll
    for (int s = 1; s < GHKS; s++) {
        float4 a = *(const float4*)(ghp + s*MN + base);
        float4 c = *(const float4*)(ghp + s*MN + base + UU);
        float4 d = *(const float4*)(ghp + s*MN + base + 2*UU);
        gr.x+=a.x; gr.y+=a.y; gr.z+=a.z; gr.w+=a.w;
        gz.x+=c.x; gz.y+=c.y; gz.z+=c.z; gz.w+=c.w;
        gn.x+=d.x; gn.y+=d.y; gn.z+=d.z; gn.w+=d.w;
    }
    float4 ir = *(const float4*)(gi + base);
    float4 iz = *(const float4*)(gi + base + UU);
    float4 in = *(const float4*)(gi + base + 2*UU);
    float4 hv = *(const float4*)(h + (size_t)b*UU + u);
    float4 hn;
    {
        float r, z, n;
        r = fsigm(ir.x+gr.x); z = fsigm(iz.x+gz.x); n = ftanh(in.x + r*gn.x); hn.x = (1.f-z)*n + z*hv.x;
        r = fsigm(ir.y+gr.y); z = fsigm(iz.y+gz.y); n = ftanh(in.y + r*gn.y); hn.y = (1.f-z)*n + z*hv.y;
        r = fsigm(ir.z+gr.z); z = fsigm(iz.z+gz.z); n = ftanh(in.z + r*gn.z); hn.z = (1.f-z)*n + z*hv.z;
        r = fsigm(ir.w+gr.w); z = fsigm(iz.w+gz.w); n = ftanh(in.w + r*gn.w); hn.w = (1.f-z)*n + z*hv.w;
    }
    *(float4*)(h + (size_t)b*UU + u)         = hn;
    *(float4*)(enc_out_t + (size_t)b*UU + u) = hn;
}

// ---------------- decoder GRU gate (float4; gi partials + emb table + qgh partials)
__global__ void dec_gate(const float* __restrict__ gip, const float* __restrict__ qghp,
                         const float* __restrict__ T, const int* __restrict__ idx,
                         float* __restrict__ h)
{
    int i = blockIdx.x * blockDim.x + threadIdx.x;       // float4 index
    int b = i >> 8;
    int u = (i & 255) << 2;
    size_t gbase = (size_t)b * G3U + u;
    const size_t MN3 = (size_t)Bz * G3U;
    const float* tb = T + (size_t)idx[b] * G3U + u;
    float4 ir = *(const float4*)(tb);
    float4 iz = *(const float4*)(tb + UU);
    float4 in = *(const float4*)(tb + 2*UU);
    #pragma unroll
    for (int s = 0; s < GIKS; s++) {
        float4 a = *(const float4*)(gip + s*MN3 + gbase);
        float4 c = *(const float4*)(gip + s*MN3 + gbase + UU);
        float4 d = *(const float4*)(gip + s*MN3 + gbase + 2*UU);
        ir.x+=a.x; ir.y+=a.y; ir.z+=a.z; ir.w+=a.w;
        iz.x+=c.x; iz.y+=c.y; iz.z+=c.z; iz.w+=c.w;
        in.x+=d.x; in.y+=d.y; in.z+=d.z; in.w+=d.w;
    }
    size_t qbase = (size_t)b * NQP + u;
    const size_t MNq = (size_t)Bz * NQP;
    float4 gr = make_float4(0,0,0,0), gz = gr, gn = gr;
    #pragma unroll
    for (int s = 0; s < QGHKS; s++) {
        float4 a = *(const float4*)(qghp + s*MNq + qbase);
        float4 c = *(const float4*)(qghp + s*MNq + qbase + UU);
        float4 d = *(const float4*)(qghp + s*MNq + qbase + 2*UU);
        gr.x+=a.x; gr.y+=a.y; gr.z+=a.z; gr.w+=a.w;
        gz.x+=c.x; gz.y+=c.y; gz.z+=c.z; gz.w+=c.w;
        gn.x+=d.x; gn.y+=d.y; gn.z+=d.z; gn.w+=d.w;
    }
    float4 hv = *(const float4*)(h + (size_t)b*UU + u);
    float4 hn;
    {
        float r, z, n;
        r = fsigm(ir.x+gr.x); z = fsigm(iz.x+gz.x); n = ftanh(in.x + r*gn.x); hn.x = (1.f-z)*n + z*hv.x;
        r = fsigm(ir.y+gr.y); z = fsigm(iz.y+gz.y); n = ftanh(in.y + r*gn.y); hn.y = (1.f-z)*n + z*hv.y;
        r = fsigm(ir.z+gr.z); z = fsigm(iz.z+gz.z); n = ftanh(in.z + r*gn.z); hn.z = (1.f-z)*n + z*hv.z;
        r = fsigm(ir.w+gr.w); z = fsigm(iz.w+gz.w); n = ftanh(in.w + r*gn.w); hn.w = (1.f-z)*n + z*hv.w;
    }
    *(float4*)(h + (size_t)b*UU + u) = hn;
}

// ------- fused attention (+ optional pred/argmax for previous step) -------------
// one block per batch element b, 256 threads.
__global__ void __launch_bounds__(256) fused_attn(
    const float* __restrict__ qghp, const float* __restrict__ enc_proj,
    const float* __restrict__ enc_out,
    const float* __restrict__ V_W, const float* __restrict__ V_b,
    const float* __restrict__ W1_b, const int* __restrict__ x_len,
    float* __restrict__ ctx,
    float* __restrict__ out_t, int* __restrict__ idx)     // out_t==null -> skip pred
{
    __shared__ float qs[UU];
    __shared__ float vs[UU];
    __shared__ float wb[UU];
    __shared__ float lg[Sn];
    __shared__ float sv[VOUTn];
    __shared__ int   si[VOUTn];
    const int b = blockIdx.x, tid = threadIdx.x;
    const int w = tid >> 5, lane = tid & 31;
    const size_t MNq = (size_t)Bz * NQP;
    const size_t qoff = (size_t)b * NQP + 3*UU;

    // ---- pred + argmax for previous step (fused; cols 4096..4223 of qghp) ----
    if (out_t) {
        if (tid < VOUTn) {
            size_t base = (size_t)b * NQP + 4096 + tid;
            float v = 0.f;
            #pragma unroll
            for (int s = 0; s < QGHKS; s++) v += qghp[s*MNq + base];
            out_t[(size_t)b * VOUTn + tid] = v;
            sv[tid] = v; si[tid] = tid;
        }
        __syncthreads();
        #pragma unroll
        for (int off = 64; off; off >>= 1) {
            if (tid < off) {
                float v2 = sv[tid+off]; int i2 = si[tid+off];
                if (v2 > sv[tid] || (v2 == sv[tid] && i2 < si[tid])) { sv[tid] = v2; si[tid] = i2; }
            }
            __syncthreads();
        }
        if (tid == 0) idx[b] = si[0];
    }

    #pragma unroll
    for (int k = 0; k < 4; k++) {
        int u = tid + 256*k;
        float qv = 0.f;
        #pragma unroll
        for (int s = 0; s < QGHKS; s++) qv += qghp[s*MNq + qoff + u];
        qs[u] = qv;
        vs[u] = V_W[u];
        wb[u] = W1_b[u];
    }
    __syncthreads();

    const int L = x_len[b];
    for (int s = w; s < L; s += 8) {
        const float4* ep = (const float4*)(enc_proj + ((size_t)s * Bz + b) * UU);
        const float4* q4 = (const float4*)qs;
        const float4* v4 = (const float4*)vs;
        float sum = 0.f;
        #pragma unroll
        for (int it = 0; it < 8; it++) {
            int u = lane + 32*it;
            float4 e = ep[u], qq = q4[u], vv = v4[u];
            sum += ftanh(e.x + qq.x) * vv.x + ftanh(e.y + qq.y) * vv.y
                 + ftanh(e.z + qq.z) * vv.z + ftanh(e.w + qq.w) * vv.w;
        }
        #pragma unroll
        for (int off = 16; off; off >>= 1)
            sum += __shfl_down_sync(0xffffffffu, sum, off);
        if (lane == 0) lg[s] = sum + V_b[0];
    }
    if (w == 0 && L < Sn) {      // masked s: enc_proj row == W1_b analytically
        const float4* q4 = (const float4*)qs;
        const float4* v4 = (const float4*)vs;
        const float4* w4 = (const float4*)wb;
        float sum = 0.f;
        #pragma unroll
        for (int it = 0; it < 8; it++) {
            int u = lane + 32*it;
            float4 e = w4[u], qq = q4[u], vv = v4[u];
            sum += ftanh(e.x + qq.x) * vv.x + ftanh(e.y + qq.y) * vv.y
                 + ftanh(e.z + qq.z) * vv.z + ftanh(e.w + qq.w) * vv.w;
        }
        #pragma unroll
        for (int off = 16; off; off >>= 1)
            sum += __shfl_down_sync(0xffffffffu, sum, off);
        if (lane == 0) {
            float c = sum + V_b[0];
            for (int s = L; s < Sn; s++) lg[s] = c;
        }
    }
    __syncthreads();

    if (w == 0) {
        float v0 = lg[lane], v1 = lg[lane + 32];
        float mx = fmaxf(v0, v1);
        #pragma unroll
        for (int off = 16; off; off >>= 1)
            mx = fmaxf(mx, __shfl_xor_sync(0xffffffffu, mx, off));
        float e0 = f_ex2(1.4426950408889634f * (v0 - mx));
        float e1 = f_ex2(1.4426950408889634f * (v1 - mx));
        float sm = e0 + e1;
        #pragma unroll
        for (int off = 16; off; off >>= 1)
            sm += __shfl_xor_sync(0xffffffffu, sm, off);
        float inv = f_rcp(sm);
        lg[lane]      = e0 * inv;
        lg[lane + 32] = e1 * inv;
    }
    __syncthreads();

    float4 c4 = make_float4(0,0,0,0);
    const int u = tid << 2;
    for (int s = 0; s < L; s++) {
        float a = lg[s];
        float4 eo = *(const float4*)(enc_out + ((size_t)s * Bz + b) * UU + u);
        c4.x += a * eo.x; c4.y += a * eo.y; c4.z += a * eo.z; c4.w += a * eo.w;
    }
    *(float4*)(ctx + (size_t)b * UU + u) = c4;
}

// ---------------- final pred: sum QGHKS partials + write + argmax ----------------
__global__ void pred_argmax(const float* __restrict__ qghp,
                            float* __restrict__ out_t, int* __restrict__ idx)
{
    int b = blockIdx.x;
    int t = threadIdx.x;            // 128 threads
    const size_t MNq = (size_t)Bz * NQP;
    size_t base = (size_t)b * NQP + 4096 + t;
    float v = 0.f;
    #pragma unroll
    for (int s = 0; s < QGHKS; s++) v += qghp[s*MNq + base];
    out_t[(size_t)b * VOUTn + t] = v;

    __shared__ float sv[VOUTn];
    __shared__ int   si[VOUTn];
    sv[t] = v; si[t] = t;
    __syncthreads();
    #pragma unroll
    for (int off = 64; off; off >>= 1) {
        if (t < off) {
            float v2 = sv[t+off]; int i2 = si[t+off];
            if (v2 > sv[t] || (v2 == sv[t] && i2 < si[t])) { sv[t] = v2; si[t] = i2; }
        }
        __syncthreads();
    }
    if (t == 0) idx[b] = si[0];
}

// ---------------- one-time prep & init ----------------
__global__ void prep(const float* __restrict__ dec_Whh, const float* __restrict__ W2_W,
                     const float* __restrict__ fc_W,
                     const float* __restrict__ dec_bhh, const float* __restrict__ W2_b,
                     const float* __restrict__ fc_b,
                     const float* __restrict__ o2h_W,   const float* __restrict__ o2h_b,
                     float* __restrict__ Wqgh, float* __restrict__ bqgh,
                     float* __restrict__ Aemb)
{
    int i = blockIdx.x * 256 + threadIdx.x;          // 0 .. NQP*UU-1
    float wv;
    if (i < G3U*UU)            wv = dec_Whh[i];
    else if (i < (G3U+UU)*UU)  wv = W2_W[i - G3U*UU];
    else                       wv = fc_W[i - (G3U+UU)*UU];
    Wqgh[i] = wv;
    if (i < NQP) {
        float bv;
        if (i < G3U)           bv = dec_bhh[i];
        else if (i < G3U+UU)   bv = W2_b[i - G3U];
        else                   bv = fc_b[i - G3U - UU];
        bqgh[i] = bv;
    }
    if (i < VOUTn*EE) {
        int v = i / EE, e = i % EE;
        Aemb[i] = o2h_W[(size_t)e * VOUTn + v] + o2h_b[e];
    }
}

__global__ void init_all(float4* __restrict__ enc_out, float4* __restrict__ h,
                         float4* __restrict__ out0, int* __restrict__ idx)
{
    size_t i = (size_t)blockIdx.x * 256 + threadIdx.x;    // float4 idx, 0..S*B*U/4-1
    float4 zz = make_float4(0,0,0,0);
    enc_out[i] = zz;
    if (i < Bz*UU/4)    h[i] = zz;
    if (i < Bz*VOUTn/4) out0[i] = ((i & 31) == 0) ? make_float4(1,0,0,0) : zz;
    if (i < Bz)         idx[i] = 0;
}

// ---------------- driver ----------------
extern "C" void kernel_launch(void* const* d_in, const int* in_sizes, int n_in,
                              void* d_out, int out_size)
{
    const float* x       = (const float*)d_in[0];
    const int*   x_len   = (const int*)  d_in[1];
    const float* enc_Wih = (const float*)d_in[2];
    const float* enc_Whh = (const float*)d_in[3];
    const float* enc_bih = (const float*)d_in[4];
    const float* enc_bhh = (const float*)d_in[5];
    const float* dec_Wih = (const float*)d_in[6];
    const float* dec_Whh = (const float*)d_in[7];
    const float* dec_bih = (const float*)d_in[8];
    const float* dec_bhh = (const float*)d_in[9];
    const float* o2h_W   = (const float*)d_in[10];
    const float* o2h_b   = (const float*)d_in[11];
    const float* fc_W    = (const float*)d_in[12];
    const float* fc_b    = (const float*)d_in[13];
    const float* W1_W    = (const float*)d_in[14];
    const float* W1_b    = (const float*)d_in[15];
    const float* W2_W    = (const float*)d_in[16];
    const float* W2_b    = (const float*)d_in[17];
    const float* V_W     = (const float*)d_in[18];
    const float* V_b     = (const float*)d_in[19];
    float* out = (float*)d_out;

    float *gi_enc, *enc_out, *enc_proj, *h, *ghp, *gip, *qghp, *ctx;
    float *Wqgh, *bqgh, *T, *Aemb, *zerob;
    int* idx;
    cudaGetSymbolAddress((void**)&gi_enc,   g_gi_enc);
    cudaGetSymbolAddress((void**)&enc_out,  g_enc_out);
    cudaGetSymbolAddress((void**)&enc_proj, g_enc_proj);
    cudaGetSymbolAddress((void**)&h,        g_h);
    cudaGetSymbolAddress((void**)&ghp,      g_ghp);
    cudaGetSymbolAddress((void**)&gip,      g_gip);
    cudaGetSymbolAddress((void**)&qghp,     g_qghp);
    cudaGetSymbolAddress((void**)&ctx,      g_ctx);
    cudaGetSymbolAddress((void**)&idx,      g_idx);
    cudaGetSymbolAddress((void**)&Wqgh,     g_Wqgh);
    cudaGetSymbolAddress((void**)&bqgh,     g_bqgh);
    cudaGetSymbolAddress((void**)&T,        g_T);
    cudaGetSymbolAddress((void**)&Aemb,     g_Aemb);
    cudaGetSymbolAddress((void**)&zerob,    g_zero);

    // ---- one-time prep ----
    prep<<<(NQP*UU)/256, 256>>>(dec_Whh, W2_W, fc_W, dec_bhh, W2_b, fc_b,
                                o2h_W, o2h_b, Wqgh, bqgh, Aemb);
    init_all<<<((size_t)Sn*Bz*UU/4)/256, 256>>>((float4*)enc_out, (float4*)h,
                                                (float4*)out, idx);
    // emb->gi table: T[128,3U] = Aemb @ dec_Wih[:,U:U+E]^T + dec_bih
    gemm2<<<dim3(G3U/128, VOUTn/64, 1), 128>>>(Aemb, EE, dec_Wih + UU, UU+EE,
                                               dec_bih, T, VOUTn, G3U, EE, 1,
                                               nullptr, -1);
    // encoder input gates, all steps (skip fully-masked tiles)
    gemm2<<<dim3(G3U/128, (Sn*Bz)/64, 1), 128>>>(x, VIN, enc_Wih, VIN, enc_bih,
                                                 gi_enc, Sn*Bz, G3U, VIN, 1,
                                                 x_len, -1);

    // ---- Encoder: 64 sequential GRU steps (active-suffix only) ----
    for (int t = 0; t < Sn; t++) {
        gemm2<<<dim3(G3U/128, Bz/64, GHKS), 128>>>(h, UU, enc_Whh, UU, enc_bhh,
                                                   ghp, Bz, G3U, UU, GHKS,
                                                   x_len, t);
        enc_gate<<<(Bz*UU/4)/256, 256>>>(gi_enc + (size_t)t*Bz*G3U, ghp, h,
                                         enc_out + (size_t)t*Bz*UU, x_len, t);
    }

    // enc_proj = enc_out @ W1^T + b
    gemm2<<<dim3(UU/128, (Sn*Bz)/64, 1), 128>>>(enc_out, UU, W1_W, UU, W1_b,
                                                enc_proj, Sn*Bz, UU, UU, 1,
                                                x_len, -1);

    // ---- Decoder: 24 steps; [gh|q|pred] in one GEMM; pred_{k-1} fused into attn
    for (int k = 1; k <= TDEC - 1; k++) {
        gemm2<<<dim3(NQP/128, Bz/64, QGHKS), 128>>>(h, UU, Wqgh, UU, bqgh,
                                                    qghp, Bz, NQP, UU, QGHKS,
                                                    nullptr, -1);
        fused_attn<<<Bz, 256>>>(qghp, enc_proj, enc_out, V_W, V_b, W1_b,
                                x_len, ctx,
                                (k >= 2) ? out + (size_t)(k-1)*Bz*VOUTn : nullptr,
                                idx);
        gemm2<<<dim3(G3U/128, Bz/64, GIKS), 128>>>(ctx, UU, dec_Wih, UU+EE,
                                                   zerob, gip, Bz, G3U, UU,
                                                   GIKS, nullptr, -1);
        dec_gate<<<(Bz*UU/4)/256, 256>>>(gip, qghp, T, idx, h);
    }
    // final pred: fc(h_24) = out[24]
    gemm2<<<dim3(NQP/128, Bz/64, QGHKS), 128>>>(h, UU, Wqgh, UU, bqgh,
                                                qghp, Bz, NQP, UU, QGHKS,
                                                nullptr, -1);
    pred_argmax<<<Bz, 128>>>(qghp, out + (size_t)(TDEC-1)*Bz*VOUTn, idx);
}

// round 12
// speedup vs baseline: 1.1289x; 1.0044x over previous
#include <cuda_runtime.h>
#include <math.h>

typedef unsigned long long ull;

#define Sn    64
#define Bz    256
#define VIN   128
#define VOUTn 128
#define UU    1024
#define EE    512
#define TDEC  25
#define G3U   3072
#define NQP   4224            // [gh(3072) | q(1024) | pred(128)]
#define GHKS  6
#define GIKS  6
#define QGHKS 4

// ---------------- scratch (static device globals; no allocation) ----------------
__device__ float g_gi_enc[(size_t)Sn*Bz*G3U];
__device__ float g_enc_out[(size_t)Sn*Bz*UU];     // pre-zeroed; masked rows stay 0
__device__ float g_enc_proj[(size_t)Sn*Bz*UU];
__device__ float g_h[Bz*UU];
__device__ float g_ghp[(size_t)GHKS*Bz*G3U];      // encoder gh partials
__device__ float g_gip[(size_t)GIKS*Bz*G3U];      // decoder gi (ctx part) partials
__device__ float g_qghp[(size_t)QGHKS*Bz*NQP];    // decoder [gh|q|pred] partials
__device__ float g_ctx[Bz*UU];
__device__ int   g_idx[Bz];
__device__ float g_Wqgh[(size_t)NQP*UU];          // [dec_Whh; W2_W; fc_W]
__device__ float g_bqgh[NQP];                     // [dec_bhh; W2_b; fc_b]
__device__ float g_T[(size_t)VOUTn*G3U];          // emb->gi table (incl dec_bih)
__device__ float g_Aemb[VOUTn*EE];
__device__ float g_zero[G3U];                     // zero bias

// ---------------- fast (~1e-7) transcendentals ----------------
__device__ __forceinline__ float f_ex2(float x){ float r; asm("ex2.approx.f32 %0, %1;" : "=f"(r) : "f"(x)); return r; }
__device__ __forceinline__ float f_rcp(float x){ float r; asm("rcp.approx.f32 %0, %1;" : "=f"(r) : "f"(x)); return r; }
__device__ __forceinline__ float fsigm(float x){ return f_rcp(1.f + f_ex2(-1.4426950408889634f*x)); }
__device__ __forceinline__ float ftanh(float x){ return 1.f - 2.f*f_rcp(1.f + f_ex2(2.8853900817779268f*x)); }

// ---------------- f32x2 helpers ----------------
#define DUP2(d, s)       asm("mov.b64 %0, {%1, %1};" : "=l"(d) : "f"(s))
#define FMA2(c, a, b)    asm("fma.rn.f32x2 %0, %1, %2, %0;" : "+l"(c) : "l"(a), "l"(b))
#define UNPK2(lo, hi, s) asm("mov.b64 {%0, %1}, %2;" : "=f"(lo), "=f"(hi) : "l"(s))

// ---------------- FFMA2 GEMM, double-buffered smem, 1 barrier/slab --------------
// C[M,N] = A[M,K] @ W[N,K]^T (+bias on slice z==0). Block 64x128, 128 thr, 8x8/thr.
// grid=(N/128, M/64, KS); slice z -> C + z*M*N, k in [nslab*z/KS, nslab*(z+1)/KS)*16.
// sorted-x_len early exit: tstep>=0: rows=batch; tstep<0: rows=s*256+b.
__global__ void __launch_bounds__(128) gemm2(
    const float* __restrict__ A, int lda,
    const float* __restrict__ W, int ldw,
    const float* __restrict__ bias, float* __restrict__ C,
    int M, int N, int K, int KS,
    const int* __restrict__ x_len, int tstep)
{
    const int bm = blockIdx.y * 64;
    if (x_len) {
        int t_eff = (tstep >= 0) ? tstep : (bm >> 8);
        int b_hi  = (tstep >= 0) ? (bm + 63) : ((bm & 255) + 63);
        if (x_len[b_hi] <= t_eff) return;
    }

    __shared__ float As[2][16][64];
    __shared__ float Ws[2][16][128];

    const int nslab = K >> 4;
    const int z  = blockIdx.z;
    const int k0 = ((nslab *  z     ) / KS) << 4;
    const int k1 = ((nslab * (z + 1)) / KS) << 4;
    C += (size_t)z * M * N;

    const int bn  = blockIdx.x * 128;
    const int tid = threadIdx.x;
    const int ty  = tid >> 4;
    const int tx  = tid & 15;
    const int ar  = tid >> 1;
    const int ak  = (tid & 1) << 3;

    ull acc[4][8];
    #pragma unroll
    for (int i = 0; i < 4; i++)
        #pragma unroll
        for (int j = 0; j < 8; j++) acc[i][j] = 0ull;

    const float* Arow = A + (size_t)(bm + ar) * lda + ak;
    const float* Wrow = W + (size_t)(bn + tid) * ldw;

    float4 pa0 = *(const float4*)(Arow + k0);
    float4 pa1 = *(const float4*)(Arow + k0 + 4);
    float4 pw0 = *(const float4*)(Wrow + k0);
    float4 pw1 = *(const float4*)(Wrow + k0 + 4);
    float4 pw2 = *(const float4*)(Wrow + k0 + 8);
    float4 pw3 = *(const float4*)(Wrow + k0 + 12);

    int cur = 0;
    for (int kb = k0; kb < k1; kb += 16) {
        As[cur][ak+0][ar] = pa0.x; As[cur][ak+1][ar] = pa0.y; As[cur][ak+2][ar] = pa0.z; As[cur][ak+3][ar] = pa0.w;
        As[cur][ak+4][ar] = pa1.x; As[cur][ak+5][ar] = pa1.y; As[cur][ak+6][ar] = pa1.z; As[cur][ak+7][ar] = pa1.w;
        Ws[cur][ 0][tid] = pw0.x; Ws[cur][ 1][tid] = pw0.y; Ws[cur][ 2][tid] = pw0.z; Ws[cur][ 3][tid] = pw0.w;
        Ws[cur][ 4][tid] = pw1.x; Ws[cur][ 5][tid] = pw1.y; Ws[cur][ 6][tid] = pw1.z; Ws[cur][ 7][tid] = pw1.w;
        Ws[cur][ 8][tid] = pw2.x; Ws[cur][ 9][tid] = pw2.y; Ws[cur][10][tid] = pw2.z; Ws[cur][11][tid] = pw2.w;
        Ws[cur][12][tid] = pw3.x; Ws[cur][13][tid] = pw3.y; Ws[cur][14][tid] = pw3.z; Ws[cur][15][tid] = pw3.w;
        __syncthreads();

        if (kb + 16 < k1) {        // prefetch next slab; hides under compute
            pa0 = *(const float4*)(Arow + kb + 16);
            pa1 = *(const float4*)(Arow + kb + 20);
            pw0 = *(const float4*)(Wrow + kb + 16);
            pw1 = *(const float4*)(Wrow + kb + 20);
            pw2 = *(const float4*)(Wrow + kb + 24);
            pw3 = *(const float4*)(Wrow + kb + 28);
        }

        #pragma unroll
        for (int kk = 0; kk < 16; kk++) {
            const ull* ap = (const ull*)&As[cur][kk][ty << 3];
            ull a2_0 = ap[0], a2_1 = ap[1], a2_2 = ap[2], a2_3 = ap[3];
            const float* wp = &Ws[cur][kk][tx << 3];
            float4 wv0 = *(const float4*)wp;
            float4 wv1 = *(const float4*)(wp + 4);
            ull wd[8];
            DUP2(wd[0], wv0.x); DUP2(wd[1], wv0.y); DUP2(wd[2], wv0.z); DUP2(wd[3], wv0.w);
            DUP2(wd[4], wv1.x); DUP2(wd[5], wv1.y); DUP2(wd[6], wv1.z); DUP2(wd[7], wv1.w);
            #pragma unroll
            for (int j = 0; j < 8; j++) {
                FMA2(acc[0][j], a2_0, wd[j]);
                FMA2(acc[1][j], a2_1, wd[j]);
                FMA2(acc[2][j], a2_2, wd[j]);
                FMA2(acc[3][j], a2_3, wd[j]);
            }
        }
        cur ^= 1;
    }

    const int col = bn + (tx << 3);
    float bv[8];
    #pragma unroll
    for (int j = 0; j < 8; j++) bv[j] = (z == 0) ? bias[col + j] : 0.f;

    #pragma unroll
    for (int i = 0; i < 4; i++) {
        const int r0 = bm + (ty << 3) + 2*i;
        float lo[8], hi[8];
        #pragma unroll
        for (int j = 0; j < 8; j++) {
            float l, h;
            UNPK2(l, h, acc[i][j]);
            lo[j] = l + bv[j];
            hi[j] = h + bv[j];
        }
        float4* c0 = (float4*)(C + (size_t)r0     * N + col);
        float4* c1 = (float4*)(C + (size_t)(r0+1) * N + col);
        c0[0] = make_float4(lo[0], lo[1], lo[2], lo[3]);
        c0[1] = make_float4(lo[4], lo[5], lo[6], lo[7]);
        c1[0] = make_float4(hi[0], hi[1], hi[2], hi[3]);
        c1[1] = make_float4(hi[4], hi[5], hi[6], hi[7]);
    }
}

// ---------------- encoder GRU gate (float4, active rows only) ----------------
__global__ void enc_gate(const float* __restrict__ gi, const float* __restrict__ ghp,
                         float* __restrict__ h, float* __restrict__ enc_out_t,
                         const int* __restrict__ x_len, int t)
{
    int i = blockIdx.x * blockDim.x + threadIdx.x;       // float4 index, 0..Bz*UU/4
    int b = i >> 8;
    if (t >= x_len[b]) return;
    int u = (i & 255) << 2;
    size_t base = (size_t)b * G3U + u;
    const size_t MN = (size_t)Bz * G3U;
    float4 gr = *(const float4*)(ghp + base);
    float4 gz = *(const float4*)(ghp + base + UU);
    float4 gn = *(const float4*)(ghp + base + 2*UU);
    #pragma unroll
    for (int s = 1; s < GHKS; s++) {
        float4 a = *(const float4*)(ghp + s*MN + base);
        float4 c = *(const float4*)(ghp + s*MN + base + UU);
        float4 d = *(const float4*)(ghp + s*MN + base + 2*UU);
        gr.x+=a.x; gr.y+=a.y; gr.z+=a.z; gr.w+=a.w;
        gz.x+=c.x; gz.y+=c.y; gz.z+=c.z; gz.w+=c.w;
        gn.x+=d.x; gn.y+=d.y; gn.z+=d.z; gn.w+=d.w;
    }
    float4 ir = *(const float4*)(gi + base);
    float4 iz = *(const float4*)(gi + base + UU);
    float4 in = *(const float4*)(gi + base + 2*UU);
    float4 hv = *(const float4*)(h + (size_t)b*UU + u);
    float4 hn;
    {
        float r, z, n;
        r = fsigm(ir.x+gr.x); z = fsigm(iz.x+gz.x); n = ftanh(in.x + r*gn.x); hn.x = (1.f-z)*n + z*hv.x;
        r = fsigm(ir.y+gr.y); z = fsigm(iz.y+gz.y); n = ftanh(in.y + r*gn.y); hn.y = (1.f-z)*n + z*hv.y;
        r = fsigm(ir.z+gr.z); z = fsigm(iz.z+gz.z); n = ftanh(in.z + r*gn.z); hn.z = (1.f-z)*n + z*hv.z;
        r = fsigm(ir.w+gr.w); z = fsigm(iz.w+gz.w); n = ftanh(in.w + r*gn.w); hn.w = (1.f-z)*n + z*hv.w;
    }
    *(float4*)(h + (size_t)b*UU + u)         = hn;
    *(float4*)(enc_out_t + (size_t)b*UU + u) = hn;
}

// ---------------- decoder GRU gate (float4; gi partials + emb table + qgh partials)
__global__ void dec_gate(const float* __restrict__ gip, const float* __restrict__ qghp,
                         const float* __restrict__ T, const int* __restrict__ idx,
                         float* __restrict__ h)
{
    int i = blockIdx.x * blockDim.x + threadIdx.x;       // float4 index
    int b = i >> 8;
    int u = (i & 255) << 2;
    size_t gbase = (size_t)b * G3U + u;
    const size_t MN3 = (size_t)Bz * G3U;
    const float* tb = T + (size_t)idx[b] * G3U + u;
    float4 ir = *(const float4*)(tb);
    float4 iz = *(const float4*)(tb + UU);
    float4 in = *(const float4*)(tb + 2*UU);
    #pragma unroll
    for (int s = 0; s < GIKS; s++) {
        float4 a = *(const float4*)(gip + s*MN3 + gbase);
        float4 c = *(const float4*)(gip + s*MN3 + gbase + UU);
        float4 d = *(const float4*)(gip + s*MN3 + gbase + 2*UU);
        ir.x+=a.x; ir.y+=a.y; ir.z+=a.z; ir.w+=a.w;
        iz.x+=c.x; iz.y+=c.y; iz.z+=c.z; iz.w+=c.w;
        in.x+=d.x; in.y+=d.y; in.z+=d.z; in.w+=d.w;
    }
    size_t qbase = (size_t)b * NQP + u;
    const size_t MNq = (size_t)Bz * NQP;
    float4 gr = make_float4(0,0,0,0), gz = gr, gn = gr;
    #pragma unroll
    for (int s = 0; s < QGHKS; s++) {
        float4 a = *(const float4*)(qghp + s*MNq + qbase);
        float4 c = *(const float4*)(qghp + s*MNq + qbase + UU);
        float4 d = *(const float4*)(qghp + s*MNq + qbase + 2*UU);
        gr.x+=a.x; gr.y+=a.y; gr.z+=a.z; gr.w+=a.w;
        gz.x+=c.x; gz.y+=c.y; gz.z+=c.z; gz.w+=c.w;
        gn.x+=d.x; gn.y+=d.y; gn.z+=d.z; gn.w+=d.w;
    }
    float4 hv = *(const float4*)(h + (size_t)b*UU + u);
    float4 hn;
    {
        float r, z, n;
        r = fsigm(ir.x+gr.x); z = fsigm(iz.x+gz.x); n = ftanh(in.x + r*gn.x); hn.x = (1.f-z)*n + z*hv.x;
        r = fsigm(ir.y+gr.y); z = fsigm(iz.y+gz.y); n = ftanh(in.y + r*gn.y); hn.y = (1.f-z)*n + z*hv.y;
        r = fsigm(ir.z+gr.z); z = fsigm(iz.z+gz.z); n = ftanh(in.z + r*gn.z); hn.z = (1.f-z)*n + z*hv.z;
        r = fsigm(ir.w+gr.w); z = fsigm(iz.w+gz.w); n = ftanh(in.w + r*gn.w); hn.w = (1.f-z)*n + z*hv.w;
    }
    *(float4*)(h + (size_t)b*UU + u) = hn;
}

// ------- fused attention (+ optional pred/argmax for previous step) -------------
// one block per batch element b, 256 threads.
__global__ void __launch_bounds__(256) fused_attn(
    const float* __restrict__ qghp, const float* __restrict__ enc_proj,
    const float* __restrict__ enc_out,
    const float* __restrict__ V_W, const float* __restrict__ V_b,
    const float* __restrict__ W1_b, const int* __restrict__ x_len,
    float* __restrict__ ctx,
    float* __restrict__ out_t, int* __restrict__ idx)     // out_t==null -> skip pred
{
    __shared__ float qs[UU];
    __shared__ float vs[UU];
    __shared__ float wb[UU];
    __shared__ float lg[Sn];
    __shared__ float sv[VOUTn];
    __shared__ int   si[VOUTn];
    const int b = blockIdx.x, tid = threadIdx.x;
    const int w = tid >> 5, lane = tid & 31;
    const size_t MNq = (size_t)Bz * NQP;
    const size_t qoff = (size_t)b * NQP + 3*UU;

    // ---- pred + argmax for previous step (fused; cols 4096..4223 of qghp) ----
    if (out_t) {
        if (tid < VOUTn) {
            size_t base = (size_t)b * NQP + 4096 + tid;
            float v = 0.f;
            #pragma unroll
            for (int s = 0; s < QGHKS; s++) v += qghp[s*MNq + base];
            out_t[(size_t)b * VOUTn + tid] = v;
            sv[tid] = v; si[tid] = tid;
        }
        __syncthreads();
        #pragma unroll
        for (int off = 64; off; off >>= 1) {
            if (tid < off) {
                float v2 = sv[tid+off]; int i2 = si[tid+off];
                if (v2 > sv[tid] || (v2 == sv[tid] && i2 < si[tid])) { sv[tid] = v2; si[tid] = i2; }
            }
            __syncthreads();
        }
        if (tid == 0) idx[b] = si[0];
    }

    #pragma unroll
    for (int k = 0; k < 4; k++) {
        int u = tid + 256*k;
        float qv = 0.f;
        #pragma unroll
        for (int s = 0; s < QGHKS; s++) qv += qghp[s*MNq + qoff + u];
        qs[u] = qv;
        vs[u] = V_W[u];
        wb[u] = W1_b[u];
    }
    __syncthreads();

    const int L = x_len[b];
    for (int s = w; s < L; s += 8) {
        const float4* ep = (const float4*)(enc_proj + ((size_t)s * Bz + b) * UU);
        const float4* q4 = (const float4*)qs;
        const float4* v4 = (const float4*)vs;
        float sum = 0.f;
        #pragma unroll
        for (int it = 0; it < 8; it++) {
            int u = lane + 32*it;
            float4 e = ep[u], qq = q4[u], vv = v4[u];
            sum += ftanh(e.x + qq.x) * vv.x + ftanh(e.y + qq.y) * vv.y
                 + ftanh(e.z + qq.z) * vv.z + ftanh(e.w + qq.w) * vv.w;
        }
        #pragma unroll
        for (int off = 16; off; off >>= 1)
            sum += __shfl_down_sync(0xffffffffu, sum, off);
        if (lane == 0) lg[s] = sum + V_b[0];
    }
    if (w == 0 && L < Sn) {      // masked s: enc_proj row == W1_b analytically
        const float4* q4 = (const float4*)qs;
        const float4* v4 = (const float4*)vs;
        const float4* w4 = (const float4*)wb;
        float sum = 0.f;
        #pragma unroll
        for (int it = 0; it < 8; it++) {
            int u = lane + 32*it;
            float4 e = w4[u], qq = q4[u], vv = v4[u];
            sum += ftanh(e.x + qq.x) * vv.x + ftanh(e.y + qq.y) * vv.y
                 + ftanh(e.z + qq.z) * vv.z + ftanh(e.w + qq.w) * vv.w;
        }
        #pragma unroll
        for (int off = 16; off; off >>= 1)
            sum += __shfl_down_sync(0xffffffffu, sum, off);
        if (lane == 0) {
            float c = sum + V_b[0];
            for (int s = L; s < Sn; s++) lg[s] = c;
        }
    }
    __syncthreads();

    if (w == 0) {
        float v0 = lg[lane], v1 = lg[lane + 32];
        float mx = fmaxf(v0, v1);
        #pragma unroll
        for (int off = 16; off; off >>= 1)
            mx = fmaxf(mx, __shfl_xor_sync(0xffffffffu, mx, off));
        float e0 = f_ex2(1.4426950408889634f * (v0 - mx));
        float e1 = f_ex2(1.4426950408889634f * (v1 - mx));
        float sm = e0 + e1;
        #pragma unroll
        for (int off = 16; off; off >>= 1)
            sm += __shfl_xor_sync(0xffffffffu, sm, off);
        float inv = f_rcp(sm);
        lg[lane]      = e0 * inv;
        lg[lane + 32] = e1 * inv;
    }
    __syncthreads();

    float4 c4 = make_float4(0,0,0,0);
    const int u = tid << 2;
    for (int s = 0; s < L; s++) {
        float a = lg[s];
        float4 eo = *(const float4*)(enc_out + ((size_t)s * Bz + b) * UU + u);
        c4.x += a * eo.x; c4.y += a * eo.y; c4.z += a * eo.z; c4.w += a * eo.w;
    }
    *(float4*)(ctx + (size_t)b * UU + u) = c4;
}

// ---------------- final pred: sum QGHKS partials + write + argmax ----------------
__global__ void pred_argmax(const float* __restrict__ qghp,
                            float* __restrict__ out_t, int* __restrict__ idx)
{
    int b = blockIdx.x;
    int t = threadIdx.x;            // 128 threads
    const size_t MNq = (size_t)Bz * NQP;
    size_t base = (size_t)b * NQP + 4096 + t;
    float v = 0.f;
    #pragma unroll
    for (int s = 0; s < QGHKS; s++) v += qghp[s*MNq + base];
    out_t[(size_t)b * VOUTn + t] = v;

    __shared__ float sv[VOUTn];
    __shared__ int   si[VOUTn];
    sv[t] = v; si[t] = t;
    __syncthreads();
    #pragma unroll
    for (int off = 64; off; off >>= 1) {
        if (t < off) {
            float v2 = sv[t+off]; int i2 = si[t+off];
            if (v2 > sv[t] || (v2 == sv[t] && i2 < si[t])) { sv[t] = v2; si[t] = i2; }
        }
        __syncthreads();
    }
    if (t == 0) idx[b] = si[0];
}

// ---------------- one-time prep & init ----------------
__global__ void prep(const float* __restrict__ dec_Whh, const float* __restrict__ W2_W,
                     const float* __restrict__ fc_W,
                     const float* __restrict__ dec_bhh, const float* __restrict__ W2_b,
                     const float* __restrict__ fc_b,
                     const float* __restrict__ o2h_W,   const float* __restrict__ o2h_b,
                     float* __restrict__ Wqgh, float* __restrict__ bqgh,
                     float* __restrict__ Aemb)
{
    int i = blockIdx.x * 256 + threadIdx.x;          // 0 .. NQP*UU-1
    float wv;
    if (i < G3U*UU)            wv = dec_Whh[i];
    else if (i < (G3U+UU)*UU)  wv = W2_W[i - G3U*UU];
    else                       wv = fc_W[i - (G3U+UU)*UU];
    Wqgh[i] = wv;
    if (i < NQP) {
        float bv;
        if (i < G3U)           bv = dec_bhh[i];
        else if (i < G3U+UU)   bv = W2_b[i - G3U];
        else                   bv = fc_b[i - G3U - UU];
        bqgh[i] = bv;
    }
    if (i < VOUTn*EE) {
        int v = i / EE, e = i % EE;
        Aemb[i] = o2h_W[(size_t)e * VOUTn + v] + o2h_b[e];
    }
}

__global__ void init_all(float4* __restrict__ enc_out, float4* __restrict__ h,
                         float4* __restrict__ out0, int* __restrict__ idx)
{
    size_t i = (size_t)blockIdx.x * 256 + threadIdx.x;    // float4 idx, 0..S*B*U/4-1
    float4 zz = make_float4(0,0,0,0);
    enc_out[i] = zz;
    if (i < Bz*UU/4)    h[i] = zz;
    if (i < Bz*VOUTn/4) out0[i] = ((i & 31) == 0) ? make_float4(1,0,0,0) : zz;
    if (i < Bz)         idx[i] = 0;
}

// ---------------- driver ----------------
extern "C" void kernel_launch(void* const* d_in, const int* in_sizes, int n_in,
                              void* d_out, int out_size)
{
    const float* x       = (const float*)d_in[0];
    const int*   x_len   = (const int*)  d_in[1];
    const float* enc_Wih = (const float*)d_in[2];
    const float* enc_Whh = (const float*)d_in[3];
    const float* enc_bih = (const float*)d_in[4];
    const float* enc_bhh = (const float*)d_in[5];
    const float* dec_Wih = (const float*)d_in[6];
    const float* dec_Whh = (const float*)d_in[7];
    const float* dec_bih = (const float*)d_in[8];
    const float* dec_bhh = (const float*)d_in[9];
    const float* o2h_W   = (const float*)d_in[10];
    const float* o2h_b   = (const float*)d_in[11];
    const float* fc_W    = (const float*)d_in[12];
    const float* fc_b    = (const float*)d_in[13];
    const float* W1_W    = (const float*)d_in[14];
    const float* W1_b    = (const float*)d_in[15];
    const float* W2_W    = (const float*)d_in[16];
    const float* W2_b    = (const float*)d_in[17];
    const float* V_W     = (const float*)d_in[18];
    const float* V_b     = (const float*)d_in[19];
    float* out = (float*)d_out;

    float *gi_enc, *enc_out, *enc_proj, *h, *ghp, *gip, *qghp, *ctx;
    float *Wqgh, *bqgh, *T, *Aemb, *zerob;
    int* idx;
    cudaGetSymbolAddress((void**)&gi_enc,   g_gi_enc);
    cudaGetSymbolAddress((void**)&enc_out,  g_enc_out);
    cudaGetSymbolAddress((void**)&enc_proj, g_enc_proj);
    cudaGetSymbolAddress((void**)&h,        g_h);
    cudaGetSymbolAddress((void**)&ghp,      g_ghp);
    cudaGetSymbolAddress((void**)&gip,      g_gip);
    cudaGetSymbolAddress((void**)&qghp,     g_qghp);
    cudaGetSymbolAddress((void**)&ctx,      g_ctx);
    cudaGetSymbolAddress((void**)&idx,      g_idx);
    cudaGetSymbolAddress((void**)&Wqgh,     g_Wqgh);
    cudaGetSymbolAddress((void**)&bqgh,     g_bqgh);
    cudaGetSymbolAddress((void**)&T,        g_T);
    cudaGetSymbolAddress((void**)&Aemb,     g_Aemb);
    cudaGetSymbolAddress((void**)&zerob,    g_zero);

    // ---- one-time prep ----
    prep<<<(NQP*UU)/256, 256>>>(dec_Whh, W2_W, fc_W, dec_bhh, W2_b, fc_b,
                                o2h_W, o2h_b, Wqgh, bqgh, Aemb);
    init_all<<<((size_t)Sn*Bz*UU/4)/256, 256>>>((float4*)enc_out, (float4*)h,
                                                (float4*)out, idx);
    // emb->gi table: T[128,3U] = Aemb @ dec_Wih[:,U:U+E]^T + dec_bih
    gemm2<<<dim3(G3U/128, VOUTn/64, 1), 128>>>(Aemb, EE, dec_Wih + UU, UU+EE,
                                               dec_bih, T, VOUTn, G3U, EE, 1,
                                               nullptr, -1);
    // encoder input gates, all steps (skip fully-masked tiles)
    gemm2<<<dim3(G3U/128, (Sn*Bz)/64, 1), 128>>>(x, VIN, enc_Wih, VIN, enc_bih,
                                                 gi_enc, Sn*Bz, G3U, VIN, 1,
                                                 x_len, -1);

    // ---- Encoder: 64 sequential GRU steps (active-suffix only) ----
    for (int t = 0; t < Sn; t++) {
        gemm2<<<dim3(G3U/128, Bz/64, GHKS), 128>>>(h, UU, enc_Whh, UU, enc_bhh,
                                                   ghp, Bz, G3U, UU, GHKS,
                                                   x_len, t);
        enc_gate<<<(Bz*UU/4)/256, 256>>>(gi_enc + (size_t)t*Bz*G3U, ghp, h,
                                         enc_out + (size_t)t*Bz*UU, x_len, t);
    }

    // enc_proj = enc_out @ W1^T + b
    gemm2<<<dim3(UU/128, (Sn*Bz)/64, 1), 128>>>(enc_out, UU, W1_W, UU, W1_b,
                                                enc_proj, Sn*Bz, UU, UU, 1,
                                                x_len, -1);

    // ---- Decoder: 24 steps; [gh|q|pred] in one GEMM; pred_{k-1} fused into attn
    for (int k = 1; k <= TDEC - 1; k++) {
        gemm2<<<dim3(NQP/128, Bz/64, QGHKS), 128>>>(h, UU, Wqgh, UU, bqgh,
                                                    qghp, Bz, NQP, UU, QGHKS,
                                                    nullptr, -1);
        fused_attn<<<Bz, 256>>>(qghp, enc_proj, enc_out, V_W, V_b, W1_b,
                                x_len, ctx,
                                (k >= 2) ? out + (size_t)(k-1)*Bz*VOUTn : nullptr,
                                idx);
        gemm2<<<dim3(G3U/128, Bz/64, GIKS), 128>>>(ctx, UU, dec_Wih, UU+EE,
                                                   zerob, gip, Bz, G3U, UU,
                                                   GIKS, nullptr, -1);
        dec_gate<<<(Bz*UU/4)/256, 256>>>(gip, qghp, T, idx, h);
    }
    // final pred: fc(h_24) = out[24]
    gemm2<<<dim3(NQP/128, Bz/64, QGHKS), 128>>>(h, UU, Wqgh, UU, bqgh,
                                                qghp, Bz, NQP, UU, QGHKS,
                                                nullptr, -1);
    pred_argmax<<<Bz, 128>>>(qghp, out + (size_t)(TDEC-1)*Bz*VOUTn, idx);
}